// round 12
// baseline (speedup 1.0000x reference)
#include <cuda_runtime.h>
#include <cuda_bf16.h>
#include <cstdint>

// PrRoIPool2D(7,7, spatial_scale=0.5)
// features: (8, 256, 56, 56) f32 ; rois: (256,5) ; out: (256,256,7,7) f32

#define POOLED 7
#define SCALE 0.5f
#define CC 256
#define HH 56
#define WW 56
#define NSTR 9          // smem layout stride in float4 (conflict-free LDS.128)
#define NCHS 32         // channels per CTA slab
#define NTHR 128        // 32 channels x 4 pw-pair groups

__device__ __forceinline__ float tentG(float t) {
    float u;
    if (t <= 0.0f) { u = t + 1.0f; return 0.5f * u * u; }
    u = 1.0f - t;
    return 1.0f - 0.5f * u * u;
}
__device__ __forceinline__ float tent_int(float s, float e, float i) {
    float a = fminf(fmaxf(s - i, -1.0f), 1.0f);
    float b = fminf(fmaxf(e - i, -1.0f), 1.0f);
    return tentG(b) - tentG(a);
}

// ---------------- cp.async helpers ----------------
__device__ __forceinline__ void cpa16(uint32_t dst, const void* src) {
    asm volatile("cp.async.ca.shared.global [%0], [%1], 16;\n" :: "r"(dst), "l"(src));
}
__device__ __forceinline__ void cpa_commit() {
    asm volatile("cp.async.commit_group;\n");
}
template<int N>
__device__ __forceinline__ void cpa_wait() {
    asm volatile("cp.async.wait_group %0;\n" :: "n"(N));
}

struct __align__(16) SmemT {
    float4 sbuf[2][2][NCHS * NSTR];   // 2 ping-pong bufs x 2 rows (18432 B)
    float  iy[28][8];                 // per-ROI y weights (1/area folded)
    float  ixw[4][2][12];             // pair g, bin{2g,2g+1}, 12 taps
};

// ---- whole unit: staging + table fill + main loop; NSB = staged groups, NJ = window groups ----
template<int NSB, int NJ>
__device__ __forceinline__ void run_unit(
    SmemT& sm, const float* __restrict__ feat,
    int b, int c0, int base4, int hlo, int hhi, int cl, int g, int prel,
    int p0, int p1, int p2, int p3, int tid,
    float rx1, float bw, float ry1, float bh, float sc,
    float (&acc0)[POOLED], float (&acc1)[POOLED])
{
    // slot mapping: 32*NSB slots; thread owns s=tid (+ s=tid+128 if present)
    const int s0c = tid / NSB, s0j = tid - s0c * NSB;
    int i40 = base4 + s0j; if (i40 > 13) i40 = 13;
    const float* src0 = feat + (size_t)(b * CC + c0 + s0c) * (HH * WW) + i40 * 4;
    const uint32_t dst0 =
        (uint32_t)__cvta_generic_to_shared(&sm.sbuf[0][0][s0c * NSTR + s0j]);

    const float* src1 = src0; uint32_t dst1 = dst0;
    bool have1 = false;
    if constexpr (NSB > 4) {
        const int s = tid + NTHR;
        if (s < NCHS * NSB) {          // NSB=8: always; NSB=6: warps 0-1 only
            const int c = s / NSB, j = s - c * NSB;
            int i4 = base4 + j; if (i4 > 13) i4 = 13;
            src1 = feat + (size_t)(b * CC + c0 + c) * (HH * WW) + i4 * 4;
            dst1 = (uint32_t)__cvta_generic_to_shared(&sm.sbuf[0][0][c * NSTR + j]);
            have1 = true;
        }
    }
    const uint32_t rowB = NCHS * NSTR * 16;
    const uint32_t bufB = 2 * rowB;

    // prologue: rows hlo, hlo+1 (clamped) into buffer 0 as one group
    {
        const int e0 = hlo * WW;
        int e1 = (hlo + 1) * WW; const int eend = hhi * WW; if (e1 > eend) e1 = eend;
        cpa16(dst0,        src0 + e0);
        cpa16(dst0 + rowB, src0 + e1);
        if constexpr (NSB > 4) {
            if (have1) {
                cpa16(dst1,        src1 + e0);
                cpa16(dst1 + rowB, src1 + e1);
            }
        }
        cpa_commit();
    }

    // ---- fill weight tables in smem (overlapped with prologue latency) ----
    if (tid < 96) {
        const int g4 = tid / 24, rem = tid - g4 * 24, bin = rem / 12, k = rem - bin * 12;
        const int pr = (g4 == 0) ? p0 : (g4 == 1) ? p1 : (g4 == 2) ? p2 : p3;
        const int q = 2 * g4 + bin;
        float v = 0.0f;
        if (q < POOLED) {
            const int w = (base4 + pr) * 4 + k;
            if (w < WW) {
                const float xs = rx1 + q * bw;
                v = tent_int(xs, xs + bw, (float)w);
            }
        }
        sm.ixw[g4][bin][k] = v;
    }
    for (int e = tid; e < 28 * 8; e += NTHR) {
        const int hr = e >> 3, j = e & 7;
        const int h = hlo + hr;
        float v = 0.0f;
        if (j < POOLED && h <= hhi) {
            const float ys = ry1 + j * bh;
            v = sc * tent_int(ys, ys + bh, (float)h);
        }
        sm.iy[hr][j] = v;
    }
    __syncthreads();   // tables visible

    // pair weights into registers (broadcast LDS)
    float4 w0[NJ], w1[NJ];
    const float4* wp = (const float4*)&sm.ixw[g][0][0];
#pragma unroll
    for (int m = 0; m < NJ; ++m) { w0[m] = wp[m]; w1[m] = wp[3 + m]; }

    // rolling prefetch offsets (elements): rows h+2, h+3 clamped to hhi
    const int end_off = hhi * WW;
    int na_off = (hlo + 2) * WW;

    int p = 0;
    for (int h = hlo; h <= hhi; h += 2) {
        cpa_wait<0>();        // single in-flight group (this iter's rows) done
        __syncthreads();      // visibility + readers of buf p^1 finished

        // issue next iteration's rows into buffer p^1 (offsets strength-reduced)
        if (na_off <= end_off) {
            int nb_off = na_off + WW; if (nb_off > end_off) nb_off = end_off;
            const uint32_t off = (uint32_t)(p ^ 1) * bufB;
            cpa16(dst0 + off,        src0 + na_off);
            cpa16(dst0 + off + rowB, src0 + nb_off);
            if constexpr (NSB > 4) {
                if (have1) {
                    cpa16(dst1 + off,        src1 + na_off);
                    cpa16(dst1 + off + rowB, src1 + nb_off);
                }
            }
            cpa_commit();
        }
        na_off += 2 * WW;

        // y weights for both rows from smem (broadcast LDS, zero-padded tail)
        const int hr = h - hlo;
        const float4 ya0 = *(const float4*)&sm.iy[hr][0];
        const float4 yb0 = *(const float4*)&sm.iy[hr][4];
        const float4 ya1 = *(const float4*)&sm.iy[hr + 1][0];
        const float4 yb1 = *(const float4*)&sm.iy[hr + 1][4];

#pragma unroll
        for (int rr = 0; rr < 2; ++rr) {
            const float4* xv = &sm.sbuf[p][rr][cl * NSTR + prel];
            float s0 = 0.0f, s1 = 0.0f;
#pragma unroll
            for (int j = 0; j < NJ; ++j) {
                const float4 x = xv[j];
                s0 = fmaf(x.x, w0[j].x, s0); s0 = fmaf(x.y, w0[j].y, s0);
                s0 = fmaf(x.z, w0[j].z, s0); s0 = fmaf(x.w, w0[j].w, s0);
                s1 = fmaf(x.x, w1[j].x, s1); s1 = fmaf(x.y, w1[j].y, s1);
                s1 = fmaf(x.z, w1[j].z, s1); s1 = fmaf(x.w, w1[j].w, s1);
            }
            // unconditional y accumulation: iy==0 rows contribute exactly 0
            const float4 ya = rr ? ya1 : ya0;
            const float4 yb = rr ? yb1 : yb0;
            acc0[0] = fmaf(ya.x, s0, acc0[0]); acc1[0] = fmaf(ya.x, s1, acc1[0]);
            acc0[1] = fmaf(ya.y, s0, acc0[1]); acc1[1] = fmaf(ya.y, s1, acc1[1]);
            acc0[2] = fmaf(ya.z, s0, acc0[2]); acc1[2] = fmaf(ya.z, s1, acc1[2]);
            acc0[3] = fmaf(ya.w, s0, acc0[3]); acc1[3] = fmaf(ya.w, s1, acc1[3]);
            acc0[4] = fmaf(yb.x, s0, acc0[4]); acc1[4] = fmaf(yb.x, s1, acc1[4]);
            acc0[5] = fmaf(yb.y, s0, acc0[5]); acc1[5] = fmaf(yb.y, s1, acc1[5]);
            acc0[6] = fmaf(yb.z, s0, acc0[6]); acc1[6] = fmaf(yb.z, s1, acc1[6]);
        }
        p ^= 1;
    }
}

// ---------------- single fused kernel: 128 thr = 32 ch x 4 pw-pairs; grid = R*8 ----------------
__global__ __launch_bounds__(NTHR, 6)
void prroi_main(const float* __restrict__ feat, const float* __restrict__ rois,
                float* __restrict__ out)
{
    const int bid = blockIdx.x;
    const int r    = bid >> 3;
    const int c0   = (bid & 7) << 5;          // 32-channel slab
    const int tid  = threadIdx.x;
    const int cl   = tid & 31;                // channel lane
    const int g    = tid >> 5;                // pw-pair group == warp id

    __shared__ SmemT sm;

    // ---- per-ROI meta (uniform, redundant per thread; broadcast loads) ----
    const float rb  = __ldg(&rois[r * 5 + 0]);
    const float rx1 = __ldg(&rois[r * 5 + 1]) * SCALE;
    const float ry1 = __ldg(&rois[r * 5 + 2]) * SCALE;
    const float rx2 = __ldg(&rois[r * 5 + 3]) * SCALE;
    const float ry2 = __ldg(&rois[r * 5 + 4]) * SCALE;
    const int   b   = (int)rb;
    const float bw = (rx2 - rx1) * (1.0f / POOLED);
    const float bh = (ry2 - ry1) * (1.0f / POOLED);
    const float area = bw * bh;
    const float sc = (area > 0.0f) ? (1.0f / fmaxf(area, 1e-12f)) : 0.0f;

    int wlo = (int)ceilf(rx1 - 1.0f); if (wlo < 0) wlo = 0;
    const int base4 = (wlo & ~3) >> 2;                    // <= 13
    int hlo = (int)ceilf(ry1 - 1.0f);  if (hlo < 0) hlo = 0;
    int hhi = (int)floorf(ry2 + 1.0f); if (hhi > HH - 1) hhi = HH - 1;
    if (hhi < hlo) hhi = hlo;

    // per-pair relative float4 base within staged window + 8-tap qualification
    int pr[4]; int ok8 = 1;
#pragma unroll
    for (int gg = 0; gg < 4; ++gg) {
        const float xs = rx1 + (2 * gg) * bw;
        int pb = (int)ceilf(xs - 1.0f); if (pb < 0) pb = 0;
        int pb4 = (pb & ~3) >> 2; if (pb4 > 13) pb4 = 13;
        int rel = pb4 - base4;
        if (rel < 0) rel = 0;
        if (rel > 5) rel = 5;
        pr[gg] = rel;
        const float e = xs + ((gg < 3) ? 2.0f * bw : bw);
        int whi = (int)floorf(e + 1.0f); if (whi > WW - 1) whi = WW - 1;
        if (whi - (base4 + rel) * 4 > 7) ok8 = 0;
    }
    const int p0 = pr[0], p1 = pr[1], p2 = pr[2], p3 = pr[3];
    const int prel = (g == 0) ? p0 : (g == 1) ? p1 : (g == 2) ? p2 : p3;
    const int NSx = p3 + 3;                   // exact staged-group need (<= 8)

    float acc0[POOLED], acc1[POOLED];
#pragma unroll
    for (int k = 0; k < POOLED; ++k) { acc0[k] = 0.0f; acc1[k] = 0.0f; }

    if (ok8) {
        if (NSx <= 4)      run_unit<4, 2>(sm, feat, b, c0, base4, hlo, hhi, cl, g, prel, p0, p1, p2, p3, tid, rx1, bw, ry1, bh, sc, acc0, acc1);
        else if (NSx <= 6) run_unit<6, 2>(sm, feat, b, c0, base4, hlo, hhi, cl, g, prel, p0, p1, p2, p3, tid, rx1, bw, ry1, bh, sc, acc0, acc1);
        else               run_unit<8, 2>(sm, feat, b, c0, base4, hlo, hhi, cl, g, prel, p0, p1, p2, p3, tid, rx1, bw, ry1, bh, sc, acc0, acc1);
    } else {
        if (NSx <= 4)      run_unit<4, 3>(sm, feat, b, c0, base4, hlo, hhi, cl, g, prel, p0, p1, p2, p3, tid, rx1, bw, ry1, bh, sc, acc0, acc1);
        else if (NSx <= 6) run_unit<6, 3>(sm, feat, b, c0, base4, hlo, hhi, cl, g, prel, p0, p1, p2, p3, tid, rx1, bw, ry1, bh, sc, acc0, acc1);
        else               run_unit<8, 3>(sm, feat, b, c0, base4, hlo, hhi, cl, g, prel, p0, p1, p2, p3, tid, rx1, bw, ry1, bh, sc, acc0, acc1);
    }

    __syncthreads();   // all reads done before reusing smem for output gather

    // ---- gather to smem, write coalesced ----
    float* sout = (float*)&sm;                // plenty of room (>= 1568 floats)
    const int pw0 = 2 * g;
#pragma unroll
    for (int ph = 0; ph < POOLED; ++ph) {
        sout[cl * 49 + ph * 7 + pw0] = acc0[ph];
        if (pw0 + 1 < POOLED) sout[cl * 49 + ph * 7 + pw0 + 1] = acc1[ph];
    }
    __syncthreads();

    float4* o4 = (float4*)(out + ((size_t)r * CC + c0) * 49);
    const float4* s4 = (const float4*)sout;
#pragma unroll
    for (int k = 0; k < 3; ++k)
        o4[tid + NTHR * k] = s4[tid + NTHR * k];       // 384 float4
    if (tid < 8) o4[384 + tid] = s4[384 + tid];        // -> 392 = 1568 floats
}

extern "C" void kernel_launch(void* const* d_in, const int* in_sizes, int n_in,
                              void* d_out, int out_size) {
    const float* feat = (const float*)d_in[0];
    const float* rois = (const float*)d_in[1];
    float* out = (float*)d_out;
    const int R = in_sizes[1] / 5;
    prroi_main<<<R * 8, NTHR>>>(feat, rois, out);
}

// round 13
// speedup vs baseline: 1.2076x; 1.2076x over previous
#include <cuda_runtime.h>
#include <cuda.h>
#include <cuda_bf16.h>
#include <cstdint>

// PrRoIPool2D(7,7, spatial_scale=0.5)
// features: (8, 256, 56, 56) f32 ; rois: (256,5) ; out: (256,256,7,7) f32

#define POOLED 7
#define SCALE 0.5f
#define CC 256
#define HH 56
#define WW 56
#define NTHR 128        // 32 channels x 4 pw-pair groups

__device__ __forceinline__ float tentG(float t) {
    float u;
    if (t <= 0.0f) { u = t + 1.0f; return 0.5f * u * u; }
    u = 1.0f - t;
    return 1.0f - 0.5f * u * u;
}
__device__ __forceinline__ float tent_int(float s, float e, float i) {
    float a = fminf(fmaxf(s - i, -1.0f), 1.0f);
    float b = fminf(fmaxf(e - i, -1.0f), 1.0f);
    return tentG(b) - tentG(a);
}

// ---------------- mbarrier / TMA helpers ----------------
__device__ __forceinline__ void mbar_init(uint32_t a, uint32_t cnt) {
    asm volatile("mbarrier.init.shared.b64 [%0], %1;" :: "r"(a), "r"(cnt) : "memory");
}
__device__ __forceinline__ void mbar_expect(uint32_t a, uint32_t bytes) {
    asm volatile("mbarrier.arrive.expect_tx.shared.b64 _, [%0], %1;"
                 :: "r"(a), "r"(bytes) : "memory");
}
__device__ __forceinline__ void mbar_wait(uint32_t a, uint32_t parity) {
    asm volatile(
        "{\n\t.reg .pred P;\n\t"
        "MBWAIT_%=:\n\t"
        "mbarrier.try_wait.parity.acquire.cta.shared::cta.b64 P, [%0], %1, 0x989680;\n\t"
        "@!P bra MBWAIT_%=;\n\t}"
        :: "r"(a), "r"(parity) : "memory");
}
__device__ __forceinline__ void tma3d(uint32_t dst, const void* tmap,
                                      int x, int y, int z, uint32_t mbar) {
    asm volatile(
        "cp.async.bulk.tensor.3d.shared::cta.global.tile.mbarrier::complete_tx::bytes "
        "[%0], [%1, {%2, %3, %4}], [%5];"
        :: "r"(dst), "l"(tmap), "r"(x), "r"(y), "r"(z), "r"(mbar) : "memory");
}
__device__ __forceinline__ void fence_proxy() {
    asm volatile("fence.proxy.async.shared::cta;" ::: "memory");
}

// 4 row-buffers of 4KB (2 iters x 2 rows), SW128-swizzled by TMA.
// 1024B alignment so the swizzle atoms line up with buffer bases.
struct alignas(1024) SmemT {
    char  sbuf[4 * 4096];
    float iy[28][8];                  // per-ROI y weights (1/area folded)
    float ixw[4][2][12];              // pair g, bin{2g,2g+1}, 12 taps
    unsigned long long mbar[2];
};

// ---- templated unit: mbar init, table fill, TMA pipeline, main loop ----
template<int NJ>
__device__ __forceinline__ void run_unit(
    SmemT& sm, const void* tmapp,
    int x0, int zb, int hlo, int hhi, int cl, int g, int prel, int tid,
    int base4, int p0, int p1, int p2, int p3,
    float rx1, float bw, float ry1, float bh, float sc,
    float (&acc0)[POOLED], float (&acc1)[POOLED])
{
    const uint32_t mb0 = (uint32_t)__cvta_generic_to_shared(&sm.mbar[0]);
    const uint32_t mb1 = (uint32_t)__cvta_generic_to_shared(&sm.mbar[1]);
    const uint32_t sb  = (uint32_t)__cvta_generic_to_shared(sm.sbuf);

    if (tid == 0) {
        mbar_init(mb0, 1);
        mbar_init(mb1, 1);
        fence_proxy();
    }

    // ---- fill weight tables in smem ----
    if (tid < 96) {
        const int g4 = tid / 24, rem = tid - g4 * 24, bin = rem / 12, k = rem - bin * 12;
        const int pr = (g4 == 0) ? p0 : (g4 == 1) ? p1 : (g4 == 2) ? p2 : p3;
        const int q = 2 * g4 + bin;
        float v = 0.0f;
        if (q < POOLED) {
            const int w = (base4 + pr) * 4 + k;
            if (w < WW) {
                const float xs = rx1 + q * bw;
                v = tent_int(xs, xs + bw, (float)w);
            }
        }
        sm.ixw[g4][bin][k] = v;
    }
    for (int e = tid; e < 28 * 8; e += NTHR) {
        const int hr = e >> 3, j = e & 7;
        const int h = hlo + hr;
        float v = 0.0f;
        if (j < POOLED && h <= hhi) {
            const float ys = ry1 + j * bh;
            v = sc * tent_int(ys, ys + bh, (float)h);
        }
        sm.iy[hr][j] = v;
    }
    __syncthreads();   // tables + mbar init visible

    // prologue: iters 0 (rows hlo,hlo+1) and 1 (rows hlo+2,hlo+3) — OOB rows zero-fill
    if (tid == 0) {
        mbar_expect(mb0, 8192);
        tma3d(sb,         tmapp, x0, hlo,     zb, mb0);
        tma3d(sb + 4096,  tmapp, x0, hlo + 1, zb, mb0);
        if (hlo + 2 <= hhi) {
            mbar_expect(mb1, 8192);
            tma3d(sb + 8192,  tmapp, x0, hlo + 2, zb, mb1);
            tma3d(sb + 12288, tmapp, x0, hlo + 3, zb, mb1);
        }
    }

    // pair weights into registers (broadcast LDS)
    float4 w0[NJ], w1[NJ];
    const float4* wp = (const float4*)&sm.ixw[g][0][0];
#pragma unroll
    for (int m = 0; m < NJ; ++m) { w0[m] = wp[m]; w1[m] = wp[3 + m]; }

    // SW128 reader offsets: smem row = channel cl; chunk q lands at q ^ (cl&7)
    uint32_t co[NJ];
#pragma unroll
    for (int j = 0; j < NJ; ++j)
        co[j] = (uint32_t)(((prel + j) ^ (cl & 7)) << 4);
    const char* cbase = sm.sbuf + cl * 128;

    int it = 0;
    for (int h = hlo; h <= hhi; h += 2, ++it) {
        const int p = it & 1;
        mbar_wait((p == 0) ? mb0 : mb1, (uint32_t)((it >> 1) & 1));

        const int hr = h - hlo;
        const float4 ya0 = *(const float4*)&sm.iy[hr][0];
        const float4 yb0 = *(const float4*)&sm.iy[hr][4];
        const float4 ya1 = *(const float4*)&sm.iy[hr + 1][0];
        const float4 yb1 = *(const float4*)&sm.iy[hr + 1][4];

#pragma unroll
        for (int rr = 0; rr < 2; ++rr) {
            const char* rbase = cbase + (uint32_t)(p * 2 + rr) * 4096u;
            float s0 = 0.0f, s1 = 0.0f;
#pragma unroll
            for (int j = 0; j < NJ; ++j) {
                const float4 x = *(const float4*)(rbase + co[j]);
                s0 = fmaf(x.x, w0[j].x, s0); s0 = fmaf(x.y, w0[j].y, s0);
                s0 = fmaf(x.z, w0[j].z, s0); s0 = fmaf(x.w, w0[j].w, s0);
                s1 = fmaf(x.x, w1[j].x, s1); s1 = fmaf(x.y, w1[j].y, s1);
                s1 = fmaf(x.z, w1[j].z, s1); s1 = fmaf(x.w, w1[j].w, s1);
            }
            // guarded y accumulation (R10 proven form; uniform predicates)
            const float4 ya = rr ? ya1 : ya0;
            const float4 yb = rr ? yb1 : yb0;
            if (ya.x != 0.0f) { acc0[0] = fmaf(ya.x, s0, acc0[0]); acc1[0] = fmaf(ya.x, s1, acc1[0]); }
            if (ya.y != 0.0f) { acc0[1] = fmaf(ya.y, s0, acc0[1]); acc1[1] = fmaf(ya.y, s1, acc1[1]); }
            if (ya.z != 0.0f) { acc0[2] = fmaf(ya.z, s0, acc0[2]); acc1[2] = fmaf(ya.z, s1, acc1[2]); }
            if (ya.w != 0.0f) { acc0[3] = fmaf(ya.w, s0, acc0[3]); acc1[3] = fmaf(ya.w, s1, acc1[3]); }
            if (yb.x != 0.0f) { acc0[4] = fmaf(yb.x, s0, acc0[4]); acc1[4] = fmaf(yb.x, s1, acc1[4]); }
            if (yb.y != 0.0f) { acc0[5] = fmaf(yb.y, s0, acc0[5]); acc1[5] = fmaf(yb.y, s1, acc1[5]); }
            if (yb.z != 0.0f) { acc0[6] = fmaf(yb.z, s0, acc0[6]); acc1[6] = fmaf(yb.z, s1, acc1[6]); }
        }

        __syncthreads();   // all reads of buffer p done before refilling it
        if (tid == 0 && h + 4 <= hhi) {
            const uint32_t dA = sb + (uint32_t)(p * 2) * 4096u;
            mbar_expect((p == 0) ? mb0 : mb1, 8192);
            tma3d(dA,         tmapp, x0, h + 4, zb, (p == 0) ? mb0 : mb1);
            tma3d(dA + 4096,  tmapp, x0, h + 5, zb, (p == 0) ? mb0 : mb1);
        }
    }
}

// ---------------- fused kernel: 128 thr = 32 ch x 4 pw-pairs; grid = R*8 ----------------
__global__ __launch_bounds__(NTHR, 6)
void prroi_main(const __grid_constant__ CUtensorMap tmap,
                const float* __restrict__ rois, float* __restrict__ out)
{
    const int bid = blockIdx.x;
    const int r    = bid >> 3;
    const int c0   = (bid & 7) << 5;          // 32-channel slab
    const int tid  = threadIdx.x;
    const int cl   = tid & 31;                // channel lane
    const int g    = tid >> 5;                // pw-pair group == warp id

    __shared__ SmemT sm;

    // ---- per-ROI meta (uniform; broadcast loads) ----
    const float rb  = __ldg(&rois[r * 5 + 0]);
    const float rx1 = __ldg(&rois[r * 5 + 1]) * SCALE;
    const float ry1 = __ldg(&rois[r * 5 + 2]) * SCALE;
    const float rx2 = __ldg(&rois[r * 5 + 3]) * SCALE;
    const float ry2 = __ldg(&rois[r * 5 + 4]) * SCALE;
    const int   b   = (int)rb;
    const float bw = (rx2 - rx1) * (1.0f / POOLED);
    const float bh = (ry2 - ry1) * (1.0f / POOLED);
    const float area = bw * bh;
    const float sc = (area > 0.0f) ? (1.0f / fmaxf(area, 1e-12f)) : 0.0f;

    int wlo = (int)ceilf(rx1 - 1.0f); if (wlo < 0) wlo = 0;
    const int base4 = (wlo & ~3) >> 2;                    // <= 13
    int hlo = (int)ceilf(ry1 - 1.0f);  if (hlo < 0) hlo = 0;
    int hhi = (int)floorf(ry2 + 1.0f); if (hhi > HH - 1) hhi = HH - 1;
    if (hhi < hlo) hhi = hlo;

    // per-pair relative chunk base within the 8-chunk window + 8-tap qualification
    int pr[4]; int ok8 = 1;
#pragma unroll
    for (int gg = 0; gg < 4; ++gg) {
        const float xs = rx1 + (2 * gg) * bw;
        int pb = (int)ceilf(xs - 1.0f); if (pb < 0) pb = 0;
        int pb4 = (pb & ~3) >> 2; if (pb4 > 13) pb4 = 13;
        int rel = pb4 - base4;
        if (rel < 0) rel = 0;
        if (rel > 5) rel = 5;      // window rel..rel+2 stays within 8 chunks
        pr[gg] = rel;
        const float e = xs + ((gg < 3) ? 2.0f * bw : bw);
        int whi = (int)floorf(e + 1.0f); if (whi > WW - 1) whi = WW - 1;
        if (whi - (base4 + rel) * 4 > 7) ok8 = 0;
    }
    const int p0 = pr[0], p1 = pr[1], p2 = pr[2], p3 = pr[3];
    const int prel = (g == 0) ? p0 : (g == 1) ? p1 : (g == 2) ? p2 : p3;

    const int x0 = base4 * 4;                 // element x of TMA box (OOB -> zeros)
    const int zb = b * CC + c0;               // channel-plane coordinate

    float acc0[POOLED], acc1[POOLED];
#pragma unroll
    for (int k = 0; k < POOLED; ++k) { acc0[k] = 0.0f; acc1[k] = 0.0f; }

    const void* tp = (const void*)&tmap;
    if (ok8) run_unit<2>(sm, tp, x0, zb, hlo, hhi, cl, g, prel, tid,
                         base4, p0, p1, p2, p3, rx1, bw, ry1, bh, sc, acc0, acc1);
    else     run_unit<3>(sm, tp, x0, zb, hlo, hhi, cl, g, prel, tid,
                         base4, p0, p1, p2, p3, rx1, bw, ry1, bh, sc, acc0, acc1);

    __syncthreads();   // all reads done before reusing smem for output gather

    // ---- gather to smem, write coalesced ----
    float* sout = (float*)&sm;                // >= 1568 floats available
    const int pw0 = 2 * g;
#pragma unroll
    for (int ph = 0; ph < POOLED; ++ph) {
        sout[cl * 49 + ph * 7 + pw0] = acc0[ph];
        if (pw0 + 1 < POOLED) sout[cl * 49 + ph * 7 + pw0 + 1] = acc1[ph];
    }
    __syncthreads();

    float4* o4 = (float4*)(out + ((size_t)r * CC + c0) * 49);
    const float4* s4 = (const float4*)sout;
#pragma unroll
    for (int k = 0; k < 3; ++k)
        o4[tid + NTHR * k] = s4[tid + NTHR * k];       // 384 float4
    if (tid < 8) o4[384 + tid] = s4[384 + tid];        // -> 392 = 1568 floats
}

extern "C" void kernel_launch(void* const* d_in, const int* in_sizes, int n_in,
                              void* d_out, int out_size) {
    const float* feat = (const float*)d_in[0];
    const float* rois = (const float*)d_in[1];
    float* out = (float*)d_out;
    const int R = in_sizes[1] / 5;
    const cuuint64_t nc = (cuuint64_t)in_sizes[0] / (HH * WW);   // N*C planes

    // Build the tensor map host-side each call (deterministic; no allocation).
    typedef CUresult (*PFN_encode)(CUtensorMap*, CUtensorMapDataType, cuuint32_t, void*,
        const cuuint64_t*, const cuuint64_t*, const cuuint32_t*, const cuuint32_t*,
        CUtensorMapInterleave, CUtensorMapSwizzle, CUtensorMapL2promotion,
        CUtensorMapFloatOOBfill);
    void* fp = nullptr;
#if CUDART_VERSION >= 12050
    cudaDriverEntryPointQueryResult qres;
    cudaGetDriverEntryPointByVersion("cuTensorMapEncodeTiled", &fp, 12000,
                                     cudaEnableDefault, &qres);
#else
    cudaDriverEntryPointQueryResult qres;
    cudaGetDriverEntryPoint("cuTensorMapEncodeTiled", &fp, cudaEnableDefault, &qres);
#endif
    CUtensorMap tmap;
    cuuint64_t dims[3]    = { WW, HH, nc };
    cuuint64_t strides[2] = { WW * 4ull, (cuuint64_t)HH * WW * 4ull };
    cuuint32_t box[3]     = { 32, 1, 32 };     // 128B x-window, 1 row, 32 channels
    cuuint32_t estr[3]    = { 1, 1, 1 };
    ((PFN_encode)fp)(&tmap, CU_TENSOR_MAP_DATA_TYPE_FLOAT32, 3, (void*)feat,
                     dims, strides, box, estr,
                     CU_TENSOR_MAP_INTERLEAVE_NONE, CU_TENSOR_MAP_SWIZZLE_128B,
                     CU_TENSOR_MAP_L2_PROMOTION_L2_128B,
                     CU_TENSOR_MAP_FLOAT_OOB_FILL_NONE);

    prroi_main<<<R * 8, NTHR>>>(tmap, rois, out);
}